// round 3
// baseline (speedup 1.0000x reference)
#include <cuda_runtime.h>

#define BB 4
#define HH 8
#define SS 2048
#define DM 512
#define DH 64
#define TQ 16
#define TK 256

// smem floats: scores 16x2049, K/V tile 256x65, Q tile 16x64, partials 64x64
#define SMEM_FLOATS (16*2049 + 256*65 + 16*64 + 4*16*64)
#define SMEM_BYTES (SMEM_FLOATS * 4)

// ---- scratch (static device allocs: allowed; cudaMalloc is not) ----
__device__ float g_Qp[BB*SS*DM];
__device__ float g_Kp[BB*SS*DM];
__device__ float g_Vp[BB*SS*DM];
__device__ float g_ctx[BB*SS*DM];
__device__ float g_x[BB*SS*DM];
__device__ int   g_mask_mode;   // 0=uint8, 1=float32, 2=int32

// ============================================================================
// Detect the on-device dtype of the bool attention_mask.
// float32 1.0f = 0x3F800000; int32 1 = 0x00000001; uint8 packs 4 elems/word.
// With a random 0/1 mask the first 1024 words disambiguate with prob ~1-2^-1024.
// Deterministic for fixed inputs (graph-safe).
// ============================================================================
__global__ void detect_mask_mode(const unsigned int* __restrict__ m) {
    if (threadIdx.x == 0) {
        bool f01 = true, i01 = true;
        for (int i = 0; i < 1024; ++i) {
            const unsigned int w = m[i];
            if (w != 0u && w != 0x3F800000u) f01 = false;
            if (w != 0u && w != 1u)          i01 = false;
        }
        g_mask_mode = f01 ? 1 : (i01 ? 2 : 0);
    }
}

// ============================================================================
// C[M,512] = A[M,512] @ W[512,512]^T (+ optional residual), W is [out,in]
// 64x64 block tile, 256 threads, 4x4 per thread, K-tile 16.
// ============================================================================
__global__ __launch_bounds__(256) void gemm512(
        const float* __restrict__ A, const float* __restrict__ W,
        const float* __restrict__ resid, float* __restrict__ C) {
    __shared__ float As[64][17];
    __shared__ float Ws[64][17];
    const int m0 = blockIdx.y * 64;
    const int n0 = blockIdx.x * 64;
    const int t  = threadIdx.x;
    const int tx = t & 15, ty = t >> 4;
    const int lrow = t >> 2, lc4 = (t & 3) << 2;
    float acc[4][4] = {};
    for (int k0 = 0; k0 < 512; k0 += 16) {
        float4 av = *(const float4*)(A + (size_t)(m0 + lrow) * 512 + k0 + lc4);
        float4 wv = *(const float4*)(W + (size_t)(n0 + lrow) * 512 + k0 + lc4);
        As[lrow][lc4+0] = av.x; As[lrow][lc4+1] = av.y;
        As[lrow][lc4+2] = av.z; As[lrow][lc4+3] = av.w;
        Ws[lrow][lc4+0] = wv.x; Ws[lrow][lc4+1] = wv.y;
        Ws[lrow][lc4+2] = wv.z; Ws[lrow][lc4+3] = wv.w;
        __syncthreads();
        #pragma unroll
        for (int kk = 0; kk < 16; ++kk) {
            float a[4], bv[4];
            #pragma unroll
            for (int i = 0; i < 4; ++i) a[i] = As[ty + 16*i][kk];
            #pragma unroll
            for (int j = 0; j < 4; ++j) bv[j] = Ws[tx + 16*j][kk];
            #pragma unroll
            for (int i = 0; i < 4; ++i)
                #pragma unroll
                for (int j = 0; j < 4; ++j)
                    acc[i][j] = fmaf(a[i], bv[j], acc[i][j]);
        }
        __syncthreads();
    }
    #pragma unroll
    for (int i = 0; i < 4; ++i) {
        const int m = m0 + ty + 16*i;
        #pragma unroll
        for (int j = 0; j < 4; ++j) {
            const int n = n0 + tx + 16*j;
            float v = acc[i][j];
            if (resid) v += resid[(size_t)m * 512 + n];
            C[(size_t)m * 512 + n] = v;
        }
    }
}

// ============================================================================
// Fused attention per (b, h, 16-query tile):
//   scores = Q K^T * 1/8  (full 16x2048 strip kept in smem)
//   mask -> softmax -> write attn (only global write of attn, never re-read)
//   context = P @ V      (key-split x4 partials, smem reduce)
// Projection buffers ARE the [B,H,S,64] tensors (buggy reshape is a view).
// ============================================================================
__global__ __launch_bounds__(256) void attn_fused(
        const float* __restrict__ Qp, const float* __restrict__ Kp,
        const float* __restrict__ Vp, const void* __restrict__ mask,
        float* __restrict__ attn_out, float* __restrict__ ctx_out) {
    extern __shared__ float smem[];
    float* Ss  = smem;                 // [16][2049]
    float* KVs = Ss + 16 * 2049;       // [256][65]  (K tiles, then V tiles)
    float* Qs  = KVs + 256 * 65;       // [16][64]
    float* Cp  = Qs + 16 * 64;         // [64][64] partial context

    const int bh = blockIdx.y;               // b*8 + h
    const int b  = bh >> 3;
    const int h  = bh & 7;
    const int q0 = blockIdx.x * TQ;
    const float* Qbase = Qp + (size_t)bh * SS * DH;
    const float* Kbase = Kp + (size_t)bh * SS * DH;
    const float* Vbase = Vp + (size_t)bh * SS * DH;
    const int t = threadIdx.x;

    // load Q tile [16][64]
    {
        const int r = t >> 4, c = (t & 15) << 2;
        float4 v = *(const float4*)(Qbase + (size_t)(q0 + r) * DH + c);
        *(float4*)(Qs + r * DH + c) = v;
    }

    // ---- scores: tile 16q x 256k per step, thread = 4q x 4k ----
    const int kx  = t & 63;
    const int tyq = t >> 6;
    for (int kb = 0; kb < SS; kb += TK) {
        __syncthreads();
        #pragma unroll
        for (int idx = t * 4; idx < TK * DH; idx += 1024) {
            const int key = idx >> 6, d = idx & 63;
            float4 v = *(const float4*)(Kbase + (size_t)(kb + key) * DH + d);
            float* dst = KVs + key * 65 + d;
            dst[0] = v.x; dst[1] = v.y; dst[2] = v.z; dst[3] = v.w;
        }
        __syncthreads();
        float acc[4][4] = {};
        #pragma unroll 8
        for (int d = 0; d < DH; ++d) {
            float a[4], kv[4];
            #pragma unroll
            for (int i = 0; i < 4; ++i) a[i] = Qs[(tyq * 4 + i) * DH + d];
            #pragma unroll
            for (int j = 0; j < 4; ++j) kv[j] = KVs[(kx + 64 * j) * 65 + d];
            #pragma unroll
            for (int i = 0; i < 4; ++i)
                #pragma unroll
                for (int j = 0; j < 4; ++j)
                    acc[i][j] = fmaf(a[i], kv[j], acc[i][j]);
        }
        #pragma unroll
        for (int i = 0; i < 4; ++i)
            #pragma unroll
            for (int j = 0; j < 4; ++j)
                Ss[(tyq * 4 + i) * 2049 + kb + kx + 64 * j] = acc[i][j] * 0.125f;
    }
    __syncthreads();

    // ---- masked softmax: 8 warps x 2 rows ----
    {
        const int w = t >> 5, lane = t & 31;
        const int mode = g_mask_mode;
        const float*         mF = (const float*)mask;
        const int*           mI = (const int*)mask;
        const unsigned char* mU = (const unsigned char*)mask;
        #pragma unroll
        for (int rr = 0; rr < 2; ++rr) {
            const int q = w * 2 + rr;
            const size_t roff = ((size_t)b * SS + q0 + q) * SS;
            float* srow = Ss + q * 2049;
            float mx = -3.0e38f;
            for (int k = lane; k < SS; k += 32) {
                bool msk;
                if (mode == 1)      msk = (mF[roff + k] != 0.0f);
                else if (mode == 2) msk = (mI[roff + k] != 0);
                else                msk = (mU[roff + k] != 0);
                const float v = msk ? -1.0e9f : srow[k];
                srow[k] = v;
                mx = fmaxf(mx, v);
            }
            #pragma unroll
            for (int off = 16; off; off >>= 1)
                mx = fmaxf(mx, __shfl_xor_sync(0xffffffffu, mx, off));
            float sum = 0.0f;
            for (int k = lane; k < SS; k += 32) {
                const float e = __expf(srow[k] - mx);
                srow[k] = e;
                sum += e;
            }
            #pragma unroll
            for (int off = 16; off; off >>= 1)
                sum += __shfl_xor_sync(0xffffffffu, sum, off);
            const float inv = 1.0f / sum;
            float* arow = attn_out + ((size_t)bh * SS + q0 + q) * SS;
            for (int k = lane; k < SS; k += 32) {
                const float p = srow[k] * inv;
                srow[k] = p;
                arow[k] = p;
            }
        }
    }

    // ---- context: tile 16q x 64d, key-split into 4 groups, 4x4 per thread ----
    const int g  = t >> 6;       // key subgroup
    const int l  = t & 63;
    const int qy = l >> 4, dx = l & 15;
    float cacc[4][4] = {};
    for (int kb = 0; kb < SS; kb += TK) {
        __syncthreads();
        #pragma unroll
        for (int idx = t * 4; idx < TK * DH; idx += 1024) {
            const int key = idx >> 6, d = idx & 63;
            float4 v = *(const float4*)(Vbase + (size_t)(kb + key) * DH + d);
            float* dst = KVs + key * 65 + d;
            dst[0] = v.x; dst[1] = v.y; dst[2] = v.z; dst[3] = v.w;
        }
        __syncthreads();
        #pragma unroll 8
        for (int kk0 = 0; kk0 < 64; ++kk0) {
            const int kk = g * 64 + kk0;
            float p[4], vv[4];
            #pragma unroll
            for (int i = 0; i < 4; ++i) p[i] = Ss[(qy + 4 * i) * 2049 + kb + kk];
            #pragma unroll
            for (int j = 0; j < 4; ++j) vv[j] = KVs[kk * 65 + dx + 16 * j];
            #pragma unroll
            for (int i = 0; i < 4; ++i)
                #pragma unroll
                for (int j = 0; j < 4; ++j)
                    cacc[i][j] = fmaf(p[i], vv[j], cacc[i][j]);
        }
    }
    #pragma unroll
    for (int i = 0; i < 4; ++i)
        #pragma unroll
        for (int j = 0; j < 4; ++j)
            Cp[(g * 16 + qy + 4 * i) * 64 + dx + 16 * j] = cacc[i][j];
    __syncthreads();
    // reduce partials and scatter to transposed context layout [B,S,H*64]
    for (int idx = t; idx < TQ * DH; idx += 256) {
        const int q = idx >> 6, d = idx & 63;
        const float v = Cp[q * 64 + d] + Cp[(16 + q) * 64 + d] +
                        Cp[(32 + q) * 64 + d] + Cp[(48 + q) * 64 + d];
        ctx_out[((size_t)b * SS + q0 + q) * DM + h * DH + d] = v;
    }
}

// ============================================================================
// LayerNorm over last dim (512), one block (128 threads) per row
// ============================================================================
__global__ __launch_bounds__(128) void ln512(
        const float* __restrict__ x, const float* __restrict__ gamma,
        const float* __restrict__ beta, float* __restrict__ out) {
    __shared__ float sh[8];
    const int row = blockIdx.x;
    const int t = threadIdx.x;
    const float* xr = x + (size_t)row * DM;
    float4 v = *(const float4*)(xr + t * 4);
    float s  = v.x + v.y + v.z + v.w;
    float s2 = v.x * v.x + v.y * v.y + v.z * v.z + v.w * v.w;
    #pragma unroll
    for (int off = 16; off; off >>= 1) {
        s  += __shfl_xor_sync(0xffffffffu, s,  off);
        s2 += __shfl_xor_sync(0xffffffffu, s2, off);
    }
    if ((t & 31) == 0) { sh[t >> 5] = s; sh[4 + (t >> 5)] = s2; }
    __syncthreads();
    s  = sh[0] + sh[1] + sh[2] + sh[3];
    s2 = sh[4] + sh[5] + sh[6] + sh[7];
    const float mean = s * (1.0f / 512.0f);
    const float var  = s2 * (1.0f / 512.0f) - mean * mean;
    const float r    = rsqrtf(var + 1e-5f);
    float4 gv = *(const float4*)(gamma + t * 4);
    float4 bv = *(const float4*)(beta + t * 4);
    float4 o;
    o.x = (v.x - mean) * r * gv.x + bv.x;
    o.y = (v.y - mean) * r * gv.y + bv.y;
    o.z = (v.z - mean) * r * gv.z + bv.z;
    o.w = (v.w - mean) * r * gv.w + bv.w;
    *(float4*)(out + (size_t)row * DM + t * 4) = o;
}

// ============================================================================
extern "C" void kernel_launch(void* const* d_in, const int* in_sizes, int n_in,
                              void* d_out, int out_size) {
    (void)in_sizes; (void)n_in; (void)out_size;
    const float* input_Q = (const float*)d_in[0];
    const float* input_K = (const float*)d_in[1];
    const float* input_V = (const float*)d_in[2];
    const void*  mask    = d_in[3];
    const float* W_Q     = (const float*)d_in[4];
    const float* W_K     = (const float*)d_in[5];
    // d_in[6] = W_V is intentionally unused (reference bug: V projected with W_K)
    const float* W_fc    = (const float*)d_in[7];
    const float* gamma   = (const float*)d_in[8];
    const float* beta    = (const float*)d_in[9];

    float* out       = (float*)d_out;
    float* normed    = out;                              // 4*2048*512 floats
    float* attn_out  = out + (size_t)BB * SS * DM;       // 4*8*2048*2048 floats

    float *Qp, *Kp, *Vp, *ctx, *x;
    cudaGetSymbolAddress((void**)&Qp,  g_Qp);
    cudaGetSymbolAddress((void**)&Kp,  g_Kp);
    cudaGetSymbolAddress((void**)&Vp,  g_Vp);
    cudaGetSymbolAddress((void**)&ctx, g_ctx);
    cudaGetSymbolAddress((void**)&x,   g_x);

    detect_mask_mode<<<1, 32>>>((const unsigned int*)mask);

    const dim3 gg(DM / 64, (BB * SS) / 64);   // 8 x 128
    gemm512<<<gg, 256>>>(input_Q, W_Q, nullptr, Qp);
    gemm512<<<gg, 256>>>(input_K, W_K, nullptr, Kp);
    gemm512<<<gg, 256>>>(input_V, W_K, nullptr, Vp);   // W_K, per source bug

    cudaFuncSetAttribute(attn_fused,
                         cudaFuncAttributeMaxDynamicSharedMemorySize, SMEM_BYTES);
    attn_fused<<<dim3(SS / TQ, BB * HH), 256, SMEM_BYTES>>>(
        Qp, Kp, Vp, mask, attn_out, ctx);

    gemm512<<<gg, 256>>>(ctx, W_fc, input_Q, x);       // fused residual
    ln512<<<BB * SS, 128>>>(x, gamma, beta, normed);
}